// round 7
// baseline (speedup 1.0000x reference)
#include <cuda_runtime.h>
#include <cuda_fp16.h>

#define D 64
#define NMAX 100000
#define EMAX 1000000
#define GRID 444          // 148 SMs x 3 blocks, guaranteed co-resident
#define TPB 256
#define TILE 64
#define XP 65

// Scratch (allocation-free rule: __device__ globals; zero-init at load,
// trailing phase re-zeros counters -> deterministic across replays)
__device__ int      g_cnt_out[NMAX];
__device__ int      g_cnt_in[NMAX];
__device__ float    g_isq_out[NMAX];
__device__ float    g_isq_in[NMAX];
__device__ int      g_row_off[NMAX + 1];
__device__ int      g_fill[NMAX];
__device__ int      g_csr[EMAX];
__device__ __half2  g_xh[(size_t)NMAX * 32];   // x * isq_out, fp16
__device__ __half2  g_h1h[(size_t)NMAX * 32];  // h1 * isq_out, fp16
__device__ int      g_part[GRID];
__device__ unsigned g_bar_cnt;                 // grid barrier arrive counter
__device__ unsigned g_bar_gen;                 // grid barrier generation

// ---------------------------------------------------------------------------
// packed f32x2 helpers (Blackwell FFMA2 — only reachable via PTX)
// ---------------------------------------------------------------------------
__device__ __forceinline__ unsigned long long pack2(float lo, float hi) {
    unsigned long long r;
    asm("mov.b64 %0, {%1, %2};" : "=l"(r) : "f"(lo), "f"(hi));
    return r;
}
__device__ __forceinline__ void unpack2(unsigned long long v, float& lo, float& hi) {
    asm("mov.b64 {%0, %1}, %2;" : "=f"(lo), "=f"(hi) : "l"(v));
}
__device__ __forceinline__ unsigned long long fma2(unsigned long long a,
                                                   unsigned long long b,
                                                   unsigned long long c) {
    unsigned long long d;
    asm("fma.rn.f32x2 %0, %1, %2, %3;" : "=l"(d) : "l"(a), "l"(b), "l"(c));
    return d;
}

// ---------------------------------------------------------------------------
// Grid-wide barrier. All GRID blocks co-resident (launch bounds + smem sizing
// guarantee 3 blocks/SM on 148 SMs). Generation is monotonic across graph
// replays; every block reads the same base value at kernel entry.
// ---------------------------------------------------------------------------
__device__ __forceinline__ void grid_bar(unsigned target) {
    __threadfence();        // release this thread's stores
    __syncthreads();
    if (threadIdx.x == 0) {
        if (atomicAdd(&g_bar_cnt, 1u) == GRID - 1u) {
            atomicExch(&g_bar_cnt, 0u);
            __threadfence();
            atomicExch(&g_bar_gen, target);
        } else {
            while (*((volatile unsigned*)&g_bar_gen) != target) { }
            __threadfence();    // acquire
        }
    }
    __syncthreads();
}

// ---------------------------------------------------------------------------
// One GCN layer: tile-strided fused aggregate + 64x64 GEMM (+ classifier).
// Tile = 64 nodes. Aggregation: warp w owns 8 nodes serially; lane l sums
// cols 2l,2l+1 of fp16 pre-scaled source rows, then * isq_in, into sX.
// GEMM: warp -> col quarter q=w&3 (W loads warp-uniform broadcast); thread =
// 1 node x 16 cols via packed f32x2 FMA.
// ---------------------------------------------------------------------------
template <bool FUSE>
__device__ void layer_pass(const __half2* __restrict__ xin,
                           const float* __restrict__ Wg,
                           const float* __restrict__ bg,
                           const float* __restrict__ Wc,
                           const float* __restrict__ bc,
                           __half2* __restrict__ outh,
                           float* __restrict__ outf,
                           int N,
                           float* sW, float* sX, float* sCls, float* sWc) {
    int tid = threadIdx.x;
    int w = tid >> 5;
    int lane = tid & 31;
    int q = w & 3;                 // column quarter (warp-uniform)
    int g = w >> 2;                // node half within tile

    for (int i = tid; i < D * D; i += TPB) sW[i] = Wg[i];
    if (FUSE && tid < D * 2) sWc[tid] = Wc[tid];
    __syncthreads();

    int ntiles = (N + TILE - 1) / TILE;
    for (int t = blockIdx.x; t < ntiles; t += GRID) {
        int nb = t * TILE;

        // ---- aggregation into sX ----
#pragma unroll 1
        for (int nn = 0; nn < 8; nn++) {
            int local = w * 8 + nn;
            int n = nb + local;
            float ax = 0.0f, ay = 0.0f;
            if (n < N) {
                int beg = g_row_off[n];
                int end = g_row_off[n + 1];
                int e = beg;
                for (; e + 7 < end; e += 8) {
                    int s0 = g_csr[e],     s1 = g_csr[e + 1];
                    int s2 = g_csr[e + 2], s3 = g_csr[e + 3];
                    int s4 = g_csr[e + 4], s5 = g_csr[e + 5];
                    int s6 = g_csr[e + 6], s7 = g_csr[e + 7];
                    float2 f0 = __half22float2(xin[(size_t)s0 * 32 + lane]);
                    float2 f1 = __half22float2(xin[(size_t)s1 * 32 + lane]);
                    float2 f2 = __half22float2(xin[(size_t)s2 * 32 + lane]);
                    float2 f3 = __half22float2(xin[(size_t)s3 * 32 + lane]);
                    float2 f4 = __half22float2(xin[(size_t)s4 * 32 + lane]);
                    float2 f5 = __half22float2(xin[(size_t)s5 * 32 + lane]);
                    float2 f6 = __half22float2(xin[(size_t)s6 * 32 + lane]);
                    float2 f7 = __half22float2(xin[(size_t)s7 * 32 + lane]);
                    ax += (f0.x + f1.x) + (f2.x + f3.x) + (f4.x + f5.x) + (f6.x + f7.x);
                    ay += (f0.y + f1.y) + (f2.y + f3.y) + (f4.y + f5.y) + (f6.y + f7.y);
                }
                for (; e < end; e++) {
                    float2 f0 = __half22float2(xin[(size_t)g_csr[e] * 32 + lane]);
                    ax += f0.x; ay += f0.y;
                }
                float si = g_isq_in[n];
                ax *= si; ay *= si;
            }
            sX[local * XP + 2 * lane]     = ax;
            sX[local * XP + 2 * lane + 1] = ay;
        }
        __syncthreads();

        // ---- GEMM: 1 node x 16 cols per thread ----
        int local = g * 32 + lane;
        int node = nb + local;

        unsigned long long acc[8];
#pragma unroll
        for (int j = 0; j < 8; j++)
            acc[j] = pack2(bg[q * 16 + 2 * j], bg[q * 16 + 2 * j + 1]);

        unsigned wbase = (unsigned)__cvta_generic_to_shared(&sW[q * 16]);
        unsigned xbase = (unsigned)__cvta_generic_to_shared(&sX[local * XP]);

#pragma unroll 8
        for (int k = 0; k < D; k++) {
            unsigned long long w2[8];
            unsigned waddr = wbase + k * (D * 4);
            asm("ld.shared.v2.u64 {%0,%1}, [%2];" : "=l"(w2[0]), "=l"(w2[1]) : "r"(waddr));
            asm("ld.shared.v2.u64 {%0,%1}, [%2];" : "=l"(w2[2]), "=l"(w2[3]) : "r"(waddr + 16));
            asm("ld.shared.v2.u64 {%0,%1}, [%2];" : "=l"(w2[4]), "=l"(w2[5]) : "r"(waddr + 32));
            asm("ld.shared.v2.u64 {%0,%1}, [%2];" : "=l"(w2[6]), "=l"(w2[7]) : "r"(waddr + 48));
            float a;
            asm("ld.shared.f32 %0, [%1];" : "=f"(a) : "r"(xbase + k * 4));
            unsigned long long ap = pack2(a, a);
#pragma unroll
            for (int j = 0; j < 8; j++) acc[j] = fma2(ap, w2[j], acc[j]);
        }

        float v[16];
#pragma unroll
        for (int j = 0; j < 8; j++) unpack2(acc[j], v[2 * j], v[2 * j + 1]);
#pragma unroll
        for (int j = 0; j < 16; j++) v[j] = v[j] > 0.0f ? v[j] : 0.01f * v[j];

        if (!FUSE) {
            if (node < N) {
                float so = g_isq_out[node];   // fold next layer's source scale
                unsigned hp[8];
#pragma unroll
                for (int j = 0; j < 8; j++) {
                    __half2 h = __floats2half2_rn(v[2 * j] * so, v[2 * j + 1] * so);
                    hp[j] = *reinterpret_cast<unsigned*>(&h);
                }
                uint4* o = reinterpret_cast<uint4*>(outh + (size_t)node * 32 + q * 8);
                o[0] = make_uint4(hp[0], hp[1], hp[2], hp[3]);
                o[1] = make_uint4(hp[4], hp[5], hp[6], hp[7]);
            }
            __syncthreads();                  // protect sX before next tile
        } else {
            float p0 = 0.0f, p1 = 0.0f;
#pragma unroll
            for (int j = 0; j < 16; j++) {
                int f = q * 16 + j;
                p0 = fmaf(v[j], sWc[2 * f + 0], p0);
                p1 = fmaf(v[j], sWc[2 * f + 1], p1);
            }
            sCls[local * 8 + q * 2 + 0] = p0;
            sCls[local * 8 + q * 2 + 1] = p1;
            __syncthreads();
            int l2 = tid >> 1;
            int o = tid & 1;
            int nd = nb + l2;
            if (l2 < TILE && nd < N) {
                float p = sCls[l2 * 8 + 0 + o] + sCls[l2 * 8 + 2 + o]
                        + sCls[l2 * 8 + 4 + o] + sCls[l2 * 8 + 6 + o];
                outf[(size_t)nd * 2 + o] = p + bc[o];
            }
            __syncthreads();                  // protect sCls/sX before next tile
        }
    }
}

// ---------------------------------------------------------------------------
// The mega kernel: degrees -> scan -> place+prep -> layer1 -> layer2 -> zero.
// ---------------------------------------------------------------------------
__global__ __launch_bounds__(TPB, 3) void k_mega(
        const float* __restrict__ x,
        const int* __restrict__ src,
        const int* __restrict__ dst,
        const float* __restrict__ W1, const float* __restrict__ b1,
        const float* __restrict__ W2, const float* __restrict__ b2,
        const float* __restrict__ Wc, const float* __restrict__ bc,
        float* __restrict__ out, int N, int E) {
    extern __shared__ float smem[];
    float* sW   = smem;                        // 4096 floats
    float* sX   = sW + D * D;                  // TILE * XP
    float* sCls = sX + TILE * XP;              // TILE * 8
    float* sWc  = sCls + TILE * 8;             // 128
    int*   sI   = (int*)smem;                  // scan scratch (phases B only)

    int tid = threadIdx.x, bid = blockIdx.x;
    int w = tid >> 5, lane = tid & 31;
    int gtid = bid * TPB + tid;
    int gstride = GRID * TPB;

    unsigned base = *((volatile unsigned*)&g_bar_gen);

    // ---- A: degree counting ----
    for (int i = gtid; i < E; i += gstride) {
        atomicAdd(&g_cnt_out[src[i]], 1);
        atomicAdd(&g_cnt_in[dst[i]], 1);
    }
    grid_bar(base + 1);

    // ---- B1: block-local scan of in-degree + isqrt scales ----
    int n = gtid;                               // one node per thread (GRID*TPB >= N)
    int c = (n < N) ? g_cnt_in[n] : 0;
    int incl = c;
#pragma unroll
    for (int off = 1; off < 32; off <<= 1) {
        int v = __shfl_up_sync(0xffffffffu, incl, off);
        if (lane >= off) incl += v;
    }
    int excl = incl - c;
    if (lane == 31) sI[w] = incl;
    __syncthreads();
    if (w == 0) {
        int v = (lane < 8) ? sI[lane] : 0;
        int inc2 = v;
#pragma unroll
        for (int off = 1; off < 8; off <<= 1) {
            int u = __shfl_up_sync(0xffffffffu, inc2, off);
            if (lane >= off) inc2 += u;
        }
        if (lane < 8) sI[8 + lane] = inc2 - v;   // warp prefix
        if (lane == 7) g_part[bid] = inc2;       // block total
    }
    if (n < N) {
        g_isq_in[n]  = rsqrtf((float)max(c, 1));
        g_isq_out[n] = rsqrtf((float)max(g_cnt_out[n], 1));
    }
    __syncthreads();
    int excl_total = excl + sI[8 + w];
    grid_bar(base + 2);

    // ---- B2: block prefix over g_part + write row offsets ----
    {
        int p = 0;
        if (tid < bid && tid < GRID) p = g_part[tid];
        int j2 = tid + 256;
        if (j2 < bid && j2 < GRID) p += g_part[j2];
#pragma unroll
        for (int off = 16; off > 0; off >>= 1)
            p += __shfl_down_sync(0xffffffffu, p, off);
        if (lane == 0) sI[16 + w] = p;
        __syncthreads();
        if (tid == 0) {
            int s = 0;
#pragma unroll
            for (int i = 0; i < 8; i++) s += sI[16 + i];
            sI[24] = s;
        }
        __syncthreads();
        int prefix = sI[24];
        if (n < N) {
            g_row_off[n] = prefix + excl_total;
            g_fill[n] = 0;
        }
        if (gtid == 0) g_row_off[N] = E;
    }
    grid_bar(base + 3);

    // ---- C: place edges (CSR grouped by dst) + fp16 scaled feature prep ----
    for (int i = gtid; i < E; i += gstride) {
        int d = dst[i];
        int pos = g_row_off[d] + atomicAdd(&g_fill[d], 1);
        g_csr[pos] = src[i];
    }
    for (int j = gtid; j < N * 32; j += gstride) {
        int nn = j >> 5, cc = j & 31;
        float iso = g_isq_out[nn];
        float2 v = reinterpret_cast<const float2*>(x)[(size_t)nn * 32 + cc];
        g_xh[(size_t)nn * 32 + cc] = __floats2half2_rn(v.x * iso, v.y * iso);
    }
    grid_bar(base + 4);

    // ---- D: layer 1 ----
    layer_pass<false>(g_xh, W1, b1, nullptr, nullptr, g_h1h, nullptr, N,
                      sW, sX, sCls, sWc);
    grid_bar(base + 5);

    // ---- E: layer 2 + classifier ----
    layer_pass<true>(g_h1h, W2, b2, Wc, bc, nullptr, out, N,
                     sW, sX, sCls, sWc);

    // ---- F: re-zero counters for next replay (no barrier needed) ----
    for (int i = gtid; i < N; i += gstride) {
        g_cnt_out[i] = 0;
        g_cnt_in[i] = 0;
    }
}

// ---------------------------------------------------------------------------
extern "C" void kernel_launch(void* const* d_in, const int* in_sizes, int n_in,
                              void* d_out, int out_size) {
    const float* x  = (const float*)d_in[0];
    const int*   src = (const int*)d_in[1];
    const int*   dst = (const int*)d_in[2];
    const float* W1 = (const float*)d_in[3];
    const float* b1 = (const float*)d_in[4];
    const float* W2 = (const float*)d_in[5];
    const float* b2 = (const float*)d_in[6];
    const float* Wc = (const float*)d_in[7];
    const float* bc = (const float*)d_in[8];
    float* out = (float*)d_out;

    int N = in_sizes[0] / D;
    int E = in_sizes[1];

    size_t smem_bytes = (D * D + TILE * XP + TILE * 8 + 128) * sizeof(float);
    static bool attr_set = false;
    if (!attr_set) {
        cudaFuncSetAttribute(k_mega, cudaFuncAttributeMaxDynamicSharedMemorySize,
                             (int)smem_bytes);
        attr_set = true;
    }

    k_mega<<<GRID, TPB, smem_bytes>>>(x, src, dst, W1, b1, W2, b2, Wc, bc,
                                      out, N, E);
}

// round 9
// speedup vs baseline: 1.1875x; 1.1875x over previous
#include <cuda_runtime.h>
#include <cuda_fp16.h>

#define D 64
#define NMAX 100000
#define EMAX 1000000
#define XP 65
#define TILE 128
#define ECAP 3072

// Scratch (allocation-free rule: __device__ globals; zero-init at load,
// trailing k_zero restores counters -> deterministic across replays)
__device__ int     g_cnt_out[NMAX];
__device__ int     g_cnt_in[NMAX];
__device__ float   g_isq_out[NMAX];
__device__ float   g_isq_in[NMAX];
__device__ int     g_row_off[NMAX + 1];
__device__ int     g_fill[NMAX];
__device__ int     g_csr[EMAX];
__device__ __half2 g_xh[(size_t)NMAX * 32];   // x * isq_out, fp16
__device__ __half2 g_h1h[(size_t)NMAX * 32];  // h1 * isq_out, fp16
__device__ int     g_part[1024];

// ---------------------------------------------------------------------------
// packed f32x2 helpers (Blackwell FFMA2 — only reachable via PTX)
// ---------------------------------------------------------------------------
__device__ __forceinline__ unsigned long long pack2(float lo, float hi) {
    unsigned long long r;
    asm("mov.b64 %0, {%1, %2};" : "=l"(r) : "f"(lo), "f"(hi));
    return r;
}
__device__ __forceinline__ void unpack2(unsigned long long v, float& lo, float& hi) {
    asm("mov.b64 {%0, %1}, %2;" : "=f"(lo), "=f"(hi) : "l"(v));
}
__device__ __forceinline__ unsigned long long fma2(unsigned long long a,
                                                   unsigned long long b,
                                                   unsigned long long c) {
    unsigned long long d;
    asm("fma.rn.f32x2 %0, %1, %2, %3;" : "=l"(d) : "l"(a), "l"(b), "l"(c));
    return d;
}

// ---------------------------------------------------------------------------
// Build kernels
// ---------------------------------------------------------------------------
__global__ void k_deg(const int* __restrict__ src, const int* __restrict__ dst, int E) {
    int e = blockIdx.x * blockDim.x + threadIdx.x;
    if (e < E) {
        atomicAdd(&g_cnt_out[src[e]], 1);
        atomicAdd(&g_cnt_in[dst[e]], 1);
    }
}

__global__ void k_scan1(int N) {
    __shared__ int s[256];
    int t = threadIdx.x;
    int n = blockIdx.x * 256 + t;
    s[t] = (n < N) ? g_cnt_in[n] : 0;
    __syncthreads();
#pragma unroll
    for (int off = 128; off > 0; off >>= 1) {
        if (t < off) s[t] += s[t + off];
        __syncthreads();
    }
    if (t == 0) g_part[blockIdx.x] = s[0];
}

__global__ void k_scan2(int NB) {
    __shared__ int s[512];
    int t = threadIdx.x;
    s[t] = (t < NB) ? g_part[t] : 0;
    __syncthreads();
    for (int off = 1; off < 512; off <<= 1) {
        int v = (t >= off) ? s[t - off] : 0;
        __syncthreads();
        s[t] += v;
        __syncthreads();
    }
    if (t < NB) g_part[t] = (t == 0) ? 0 : s[t - 1];
}

__global__ void k_scan3(int N, int E) {
    __shared__ int s[256];
    int t = threadIdx.x;
    int n = blockIdx.x * 256 + t;
    int c = (n < N) ? g_cnt_in[n] : 0;
    s[t] = c;
    __syncthreads();
    for (int off = 1; off < 256; off <<= 1) {
        int v = (t >= off) ? s[t - off] : 0;
        __syncthreads();
        s[t] += v;
        __syncthreads();
    }
    if (n < N) {
        int excl = s[t] - c + g_part[blockIdx.x];
        g_row_off[n] = excl;
        g_fill[n] = 0;
        g_isq_in[n]  = rsqrtf((float)max(c, 1));
        g_isq_out[n] = rsqrtf((float)max(g_cnt_out[n], 1));
    }
    if (n == 0) g_row_off[N] = E;
}

__global__ void k_place_prep(const int* __restrict__ src, const int* __restrict__ dst,
                             const float* __restrict__ x, int E, int N) {
    int i = blockIdx.x * blockDim.x + threadIdx.x;
    if (i < E) {
        int d = dst[i];
        int pos = g_row_off[d] + atomicAdd(&g_fill[d], 1);
        g_csr[pos] = src[i];
    }
    int total = N * 32;
    int stride = gridDim.x * blockDim.x;
    for (int j = i; j < total; j += stride) {
        int n = j >> 5, c = j & 31;
        float iso = g_isq_out[n];
        float2 v = reinterpret_cast<const float2*>(x)[(size_t)n * 32 + c];
        g_xh[(size_t)n * 32 + c] = __floats2half2_rn(v.x * iso, v.y * iso);
    }
}

__global__ void k_zero(int N) {
    int i = blockIdx.x * blockDim.x + threadIdx.x;
    if (i < N) { g_cnt_out[i] = 0; g_cnt_in[i] = 0; }
}

// ---------------------------------------------------------------------------
// Gather-sum a node's row from fp16 table given an index list (smem or gmem).
// ---------------------------------------------------------------------------
__device__ __forceinline__ void agg_row(const __half2* __restrict__ xin,
                                        const int* __restrict__ idx, int cnt,
                                        int lane, float& ax, float& ay) {
    int e = 0;
    for (; e + 7 < cnt; e += 8) {
        int s0 = idx[e],     s1 = idx[e + 1], s2 = idx[e + 2], s3 = idx[e + 3];
        int s4 = idx[e + 4], s5 = idx[e + 5], s6 = idx[e + 6], s7 = idx[e + 7];
        float2 f0 = __half22float2(xin[(size_t)s0 * 32 + lane]);
        float2 f1 = __half22float2(xin[(size_t)s1 * 32 + lane]);
        float2 f2 = __half22float2(xin[(size_t)s2 * 32 + lane]);
        float2 f3 = __half22float2(xin[(size_t)s3 * 32 + lane]);
        float2 f4 = __half22float2(xin[(size_t)s4 * 32 + lane]);
        float2 f5 = __half22float2(xin[(size_t)s5 * 32 + lane]);
        float2 f6 = __half22float2(xin[(size_t)s6 * 32 + lane]);
        float2 f7 = __half22float2(xin[(size_t)s7 * 32 + lane]);
        ax += (f0.x + f1.x) + (f2.x + f3.x) + (f4.x + f5.x) + (f6.x + f7.x);
        ay += (f0.y + f1.y) + (f2.y + f3.y) + (f4.y + f5.y) + (f6.y + f7.y);
    }
    for (; e < cnt; e++) {
        float2 f = __half22float2(xin[(size_t)idx[e] * 32 + lane]);
        ax += f.x; ay += f.y;
    }
}

// ---------------------------------------------------------------------------
// Fused aggregate + GEMM (+ optional classifier). 256 threads, 128 nodes.
// Stage 0: bulk-copy this tile's contiguous CSR slice into smem (kills the
//   csr-load latency chain); prefetch 17 row offsets per warp via lanes+shfl.
// Stage 1: warp w owns 16 nodes; lane l sums cols 2l,2l+1.
// Stage 2: GEMM, warp -> col quarter (W loads warp-uniform broadcast),
//   thread = 2 nodes x 16 cols, packed f32x2 FMA.
// ---------------------------------------------------------------------------
template <bool FUSE>
__global__ __launch_bounds__(256, 3) void k_fused(
        const __half2* __restrict__ xin,
        const float* __restrict__ Wg,
        const float* __restrict__ bg,
        const float* __restrict__ Wc,
        const float* __restrict__ bc,
        __half2* __restrict__ out_h,
        float* __restrict__ out_f, int N) {
    extern __shared__ float smem[];
    float* sW   = smem;                     // 4096
    float* sX   = sW + D * D;               // 128 * XP
    float* sCls = sX + TILE * XP;           // 128 * 8
    float* sWc  = sCls + TILE * 8;          // 128
    int*   sE   = (int*)(sWc + 128);        // ECAP

    int tid = threadIdx.x;
    int w = tid >> 5;
    int lane = tid & 31;
    int nb = blockIdx.x * TILE;
    int tile_n = min(TILE, N - nb);

    for (int i = tid; i < D * D; i += 256) sW[i] = Wg[i];
    if (FUSE && tid < D * 2) sWc[tid] = Wc[tid];

    // ---- Stage 0: bulk edge-index copy + row-offset prefetch ----
    int beg = g_row_off[nb];
    int end = g_row_off[nb + tile_n];
    int cnt = end - beg;
    bool fits = (cnt <= ECAP);
    if (fits) {
        for (int i = tid; i < cnt; i += 256) sE[i] = g_csr[beg + i];
    }
    int roff = 0;
    {
        int nidx = nb + w * 16 + lane;      // lanes 0..16 used
        roff = g_row_off[min(nidx, N)];
    }
    __syncthreads();

    // ---- Stage 1: aggregation into sX ----
#pragma unroll 1
    for (int nn = 0; nn < 16; nn++) {
        int rb = __shfl_sync(0xffffffffu, roff, nn);
        int re = __shfl_sync(0xffffffffu, roff, nn + 1);
        float ax = 0.0f, ay = 0.0f;
        if (fits)
            agg_row(xin, sE + (rb - beg), re - rb, lane, ax, ay);
        else
            agg_row(xin, g_csr + rb, re - rb, lane, ax, ay);
        int local = w * 16 + nn;
        float si = g_isq_in[min(nb + local, N - 1)];
        sX[local * XP + 2 * lane]     = ax * si;
        sX[local * XP + 2 * lane + 1] = ay * si;
    }
    __syncthreads();

    // ---- Stage 2: GEMM ----
    int q = w & 3;                 // column quarter (warp-uniform)
    int half = w >> 2;             // node half
    int n0 = half * 64 + 2 * lane; // local node (even); thread does n0, n0+1

    unsigned long long acc[2][8];
    {
        unsigned long long binit[8];
#pragma unroll
        for (int j = 0; j < 8; j++)
            binit[j] = pack2(bg[q * 16 + 2 * j], bg[q * 16 + 2 * j + 1]);
#pragma unroll
        for (int j = 0; j < 8; j++) { acc[0][j] = binit[j]; acc[1][j] = binit[j]; }
    }

    unsigned wbase = (unsigned)__cvta_generic_to_shared(&sW[q * 16]);
    unsigned xbase0 = (unsigned)__cvta_generic_to_shared(&sX[n0 * XP]);
    unsigned xbase1 = xbase0 + XP * 4;

#pragma unroll 8
    for (int k = 0; k < D; k++) {
        unsigned long long w2[8];
        unsigned waddr = wbase + k * (D * 4);
        asm("ld.shared.v2.u64 {%0,%1}, [%2];" : "=l"(w2[0]), "=l"(w2[1]) : "r"(waddr));
        asm("ld.shared.v2.u64 {%0,%1}, [%2];" : "=l"(w2[2]), "=l"(w2[3]) : "r"(waddr + 16));
        asm("ld.shared.v2.u64 {%0,%1}, [%2];" : "=l"(w2[4]), "=l"(w2[5]) : "r"(waddr + 32));
        asm("ld.shared.v2.u64 {%0,%1}, [%2];" : "=l"(w2[6]), "=l"(w2[7]) : "r"(waddr + 48));
        float a0, a1;
        asm("ld.shared.f32 %0, [%1];" : "=f"(a0) : "r"(xbase0 + k * 4));
        asm("ld.shared.f32 %0, [%1];" : "=f"(a1) : "r"(xbase1 + k * 4));
        unsigned long long a0p = pack2(a0, a0);
        unsigned long long a1p = pack2(a1, a1);
#pragma unroll
        for (int j = 0; j < 8; j++) {
            acc[0][j] = fma2(a0p, w2[j], acc[0][j]);
            acc[1][j] = fma2(a1p, w2[j], acc[1][j]);
        }
    }

#pragma unroll
    for (int m = 0; m < 2; m++) {
        int local = n0 + m;
        int node = nb + local;
        float v[16];
#pragma unroll
        for (int j = 0; j < 8; j++) unpack2(acc[m][j], v[2 * j], v[2 * j + 1]);
#pragma unroll
        for (int j = 0; j < 16; j++) v[j] = v[j] > 0.0f ? v[j] : 0.01f * v[j];

        if (!FUSE) {
            if (node < N) {
                float so = g_isq_out[node];       // fold next layer's source scale
                unsigned hp[8];
#pragma unroll
                for (int j = 0; j < 8; j++) {
                    __half2 h = __floats2half2_rn(v[2 * j] * so, v[2 * j + 1] * so);
                    hp[j] = *reinterpret_cast<unsigned*>(&h);
                }
                uint4* o = reinterpret_cast<uint4*>(out_h + (size_t)node * 32 + q * 8);
                o[0] = make_uint4(hp[0], hp[1], hp[2], hp[3]);
                o[1] = make_uint4(hp[4], hp[5], hp[6], hp[7]);
            }
        } else {
            float p0 = 0.0f, p1 = 0.0f;
#pragma unroll
            for (int j = 0; j < 16; j++) {
                int f = q * 16 + j;
                p0 = fmaf(v[j], sWc[2 * f + 0], p0);
                p1 = fmaf(v[j], sWc[2 * f + 1], p1);
            }
            sCls[local * 8 + q * 2 + 0] = p0;
            sCls[local * 8 + q * 2 + 1] = p1;
        }
    }

    if (FUSE) {
        __syncthreads();
        int local = tid >> 1;
        int o = tid & 1;
        int node = nb + local;
        if (node < N) {
            float p = sCls[local * 8 + 0 + o] + sCls[local * 8 + 2 + o]
                    + sCls[local * 8 + 4 + o] + sCls[local * 8 + 6 + o];
            out_f[(size_t)node * 2 + o] = p + bc[o];
        }
    }
}

// ---------------------------------------------------------------------------
extern "C" void kernel_launch(void* const* d_in, const int* in_sizes, int n_in,
                              void* d_out, int out_size) {
    const float* x  = (const float*)d_in[0];
    const int*   src = (const int*)d_in[1];
    const int*   dst = (const int*)d_in[2];
    const float* W1 = (const float*)d_in[3];
    const float* b1 = (const float*)d_in[4];
    const float* W2 = (const float*)d_in[5];
    const float* b2 = (const float*)d_in[6];
    const float* Wc = (const float*)d_in[7];
    const float* bc = (const float*)d_in[8];
    float* out = (float*)d_out;

    int N = in_sizes[0] / D;
    int E = in_sizes[1];

    void *p_xh, *p_h1h;
    cudaGetSymbolAddress(&p_xh,  g_xh);
    cudaGetSymbolAddress(&p_h1h, g_h1h);

    size_t smem_bytes = (D * D + TILE * XP + TILE * 8 + 128 + ECAP) * sizeof(float);
    static bool attr_set = false;
    if (!attr_set) {
        cudaFuncSetAttribute(k_fused<false>, cudaFuncAttributeMaxDynamicSharedMemorySize,
                             (int)smem_bytes);
        cudaFuncSetAttribute(k_fused<true>, cudaFuncAttributeMaxDynamicSharedMemorySize,
                             (int)smem_bytes);
        attr_set = true;
    }

    int NB = (N + 255) / 256;   // scan blocks (<= 512)
    int gblk = (N + TILE - 1) / TILE;

    // CSR build + degree scales (counters zeroed by module init / trailing k_zero)
    k_deg<<<(E + 255) / 256, 256>>>(src, dst, E);
    k_scan1<<<NB, 256>>>(N);
    k_scan2<<<1, 512>>>(NB);
    k_scan3<<<NB, 256>>>(N, E);
    k_place_prep<<<(E + 255) / 256, 256>>>(src, dst, x, E, N);

    // layer 1: xh -> h1h (fp16, isq_out pre-folded)
    k_fused<false><<<gblk, 256, smem_bytes>>>((const __half2*)p_xh, W1, b1,
                                              nullptr, nullptr,
                                              (__half2*)p_h1h, nullptr, N);
    // layer 2 + classifier: h1h -> out
    k_fused<true><<<gblk, 256, smem_bytes>>>((const __half2*)p_h1h, W2, b2, Wc, bc,
                                             nullptr, out, N);

    // reset counters for next call
    k_zero<<<(N + 255) / 256, 256>>>(N);
}

// round 11
// speedup vs baseline: 1.3213x; 1.1127x over previous
#include <cuda_runtime.h>
#include <cuda_fp16.h>

#define D 64
#define NMAX 100000
#define EMAX 1000000
#define EPAD (EMAX + 8 * NMAX)   // padded CSR capacity
#define XP 65
#define TILE 128
#define ECAP 3072

// Scratch (allocation-free rule: __device__ globals; zero-init at load,
// layer-2 epilogue re-zeros counters -> deterministic across replays)
__device__ int     g_cnt_out[NMAX];
__device__ int     g_cnt_in[NMAX];
__device__ float   g_isq_out[NMAX];
__device__ float   g_isq_in[NMAX];
__device__ int     g_row_off[NMAX + 1];     // PADDED offsets (multiples of 8)
__device__ int     g_fill[NMAX];
__device__ int     g_csr[EPAD];
__device__ __half2 g_xh[(size_t)(NMAX + 1) * 32];   // x * isq_out fp16; row N = zeros
__device__ __half2 g_h1h[(size_t)(NMAX + 1) * 32];  // h1 * isq_out fp16; row N = zeros
__device__ int     g_part[1024];

// ---------------------------------------------------------------------------
// packed f32x2 helpers (Blackwell FFMA2 — only reachable via PTX)
// ---------------------------------------------------------------------------
__device__ __forceinline__ unsigned long long pack2(float lo, float hi) {
    unsigned long long r;
    asm("mov.b64 %0, {%1, %2};" : "=l"(r) : "f"(lo), "f"(hi));
    return r;
}
__device__ __forceinline__ void unpack2(unsigned long long v, float& lo, float& hi) {
    asm("mov.b64 {%0, %1}, %2;" : "=f"(lo), "=f"(hi) : "l"(v));
}
__device__ __forceinline__ unsigned long long fma2(unsigned long long a,
                                                   unsigned long long b,
                                                   unsigned long long c) {
    unsigned long long d;
    asm("fma.rn.f32x2 %0, %1, %2, %3;" : "=l"(d) : "l"(a), "l"(b), "l"(c));
    return d;
}

// ---------------------------------------------------------------------------
// Build kernels
// ---------------------------------------------------------------------------
__global__ void k_deg(const int* __restrict__ src, const int* __restrict__ dst, int E) {
    int e = blockIdx.x * blockDim.x + threadIdx.x;
    if (e < E) {
        atomicAdd(&g_cnt_out[src[e]], 1);
        atomicAdd(&g_cnt_in[dst[e]], 1);
    }
}

// block sums of PADDED in-degree
__global__ void k_scan1(int N) {
    __shared__ int s[256];
    int t = threadIdx.x;
    int n = blockIdx.x * 256 + t;
    s[t] = (n < N) ? ((g_cnt_in[n] + 7) & ~7) : 0;
    __syncthreads();
#pragma unroll
    for (int off = 128; off > 0; off >>= 1) {
        if (t < off) s[t] += s[t + off];
        __syncthreads();
    }
    if (t == 0) g_part[blockIdx.x] = s[0];
}

// per-block prefix over g_part (computed locally) + intra-block scan +
// row offsets + pad-entry fill + isqrt degrees + fill=0
__global__ void k_scan23(int N, int NB) {
    __shared__ int s[256];
    __shared__ int sred[8];
    int t = threadIdx.x;
    int lane = t & 31, w = t >> 5;
    int bid = blockIdx.x;
    int n = bid * 256 + t;

    // block prefix: sum of g_part[0..bid-1]
    int p = 0;
    if (t < bid) p = g_part[t];
    if (t + 256 < bid) p += g_part[t + 256];
#pragma unroll
    for (int off = 16; off > 0; off >>= 1) p += __shfl_down_sync(0xffffffffu, p, off);
    if (lane == 0) sred[w] = p;

    int c  = (n < N) ? g_cnt_in[n] : 0;
    int pc = (c + 7) & ~7;
    s[t] = pc;
    __syncthreads();
    if (t == 0) {
        int sum = 0;
#pragma unroll
        for (int i = 0; i < 8; i++) sum += sred[i];
        sred[0] = sum;
    }
    // intra-block inclusive scan of padded counts
    for (int off = 1; off < 256; off <<= 1) {
        int v = (t >= off) ? s[t - off] : 0;
        __syncthreads();
        s[t] += v;
        __syncthreads();
    }
    if (n < N) {
        int ro = sred[0] + s[t] - pc;
        g_row_off[n] = ro;
        g_fill[n] = 0;
        g_isq_in[n]  = rsqrtf((float)max(c, 1));
        g_isq_out[n] = rsqrtf((float)max(g_cnt_out[n], 1));
        // pad entries -> dummy node N (zero feature row)
        for (int j = c; j < pc; j++) g_csr[ro + j] = N;
        if (n == N - 1) g_row_off[N] = ro + pc;
    }
}

__global__ void k_place_prep(const int* __restrict__ src, const int* __restrict__ dst,
                             const float* __restrict__ x, int E, int N) {
    int i = blockIdx.x * blockDim.x + threadIdx.x;
    if (i < E) {
        int d = dst[i];
        int pos = g_row_off[d] + atomicAdd(&g_fill[d], 1);
        g_csr[pos] = src[i];
    }
    int total = N * 32;
    int stride = gridDim.x * blockDim.x;
    for (int j = i; j < total; j += stride) {
        int n = j >> 5, c = j & 31;
        float iso = g_isq_out[n];
        float2 v = reinterpret_cast<const float2*>(x)[(size_t)n * 32 + c];
        g_xh[(size_t)n * 32 + c] = __floats2half2_rn(v.x * iso, v.y * iso);
    }
}

// ---------------------------------------------------------------------------
// Pair-interleaved gather: both nodes' 8-edge batches in flight together.
// Counts are multiples of 8 (padded CSR) -> no scalar drains.
// ---------------------------------------------------------------------------
__device__ __forceinline__ void agg_pair(const __half2* __restrict__ xin,
                                         const int* __restrict__ i0, int c0,
                                         const int* __restrict__ i1, int c1,
                                         int lane,
                                         float& ax0, float& ay0,
                                         float& ax1, float& ay1) {
    int e0 = 0, e1 = 0;
    while (e0 < c0 && e1 < c1) {
        int sA[8], sB[8];
#pragma unroll
        for (int j = 0; j < 8; j++) sA[j] = i0[e0 + j];
#pragma unroll
        for (int j = 0; j < 8; j++) sB[j] = i1[e1 + j];
        __half2 hA[8], hB[8];
#pragma unroll
        for (int j = 0; j < 8; j++) hA[j] = xin[(size_t)sA[j] * 32 + lane];
#pragma unroll
        for (int j = 0; j < 8; j++) hB[j] = xin[(size_t)sB[j] * 32 + lane];
#pragma unroll
        for (int j = 0; j < 8; j++) {
            float2 f = __half22float2(hA[j]); ax0 += f.x; ay0 += f.y;
        }
#pragma unroll
        for (int j = 0; j < 8; j++) {
            float2 f = __half22float2(hB[j]); ax1 += f.x; ay1 += f.y;
        }
        e0 += 8; e1 += 8;
    }
    while (e0 < c0) {
        __half2 hA[8];
#pragma unroll
        for (int j = 0; j < 8; j++) hA[j] = xin[(size_t)i0[e0 + j] * 32 + lane];
#pragma unroll
        for (int j = 0; j < 8; j++) {
            float2 f = __half22float2(hA[j]); ax0 += f.x; ay0 += f.y;
        }
        e0 += 8;
    }
    while (e1 < c1) {
        __half2 hB[8];
#pragma unroll
        for (int j = 0; j < 8; j++) hB[j] = xin[(size_t)i1[e1 + j] * 32 + lane];
#pragma unroll
        for (int j = 0; j < 8; j++) {
            float2 f = __half22float2(hB[j]); ax1 += f.x; ay1 += f.y;
        }
        e1 += 8;
    }
}

// ---------------------------------------------------------------------------
// Fused aggregate + GEMM (+ classifier). 256 threads, 128 nodes/block.
// Stage 0: bulk-copy tile's contiguous (padded) CSR slice to smem; prefetch
//          17 row offsets per warp via lanes+shfl.
// Stage 1: warp w owns 16 nodes, processed as 8 interleaved pairs; lane l
//          accumulates cols 2l,2l+1.
// Stage 2: GEMM, warp -> col quarter (W loads warp-uniform broadcast),
//          thread = 2 nodes x 16 cols, packed f32x2 FMA.
// FUSE epilogue additionally re-zeros degree counters (replaces k_zero).
// ---------------------------------------------------------------------------
template <bool FUSE>
__global__ __launch_bounds__(256, 3) void k_fused(
        const __half2* __restrict__ xin,
        const float* __restrict__ Wg,
        const float* __restrict__ bg,
        const float* __restrict__ Wc,
        const float* __restrict__ bc,
        __half2* __restrict__ out_h,
        float* __restrict__ out_f, int N) {
    extern __shared__ float smem[];
    float* sW   = smem;                     // 4096
    float* sX   = sW + D * D;               // 128 * XP
    float* sCls = sX + TILE * XP;           // 128 * 8
    float* sWc  = sCls + TILE * 8;          // 128
    int*   sE   = (int*)(sWc + 128);        // ECAP

    int tid = threadIdx.x;
    int w = tid >> 5;
    int lane = tid & 31;
    int nb = blockIdx.x * TILE;
    int tile_n = min(TILE, N - nb);

    for (int i = tid; i < D * D; i += 256) sW[i] = Wg[i];
    if (FUSE && tid < D * 2) sWc[tid] = Wc[tid];

    // ---- Stage 0: bulk edge-index copy + row-offset prefetch ----
    int beg = g_row_off[nb];
    int end = g_row_off[nb + tile_n];
    int cnt = end - beg;
    bool fits = (cnt <= ECAP);
    if (fits) {
        for (int i = tid; i < cnt; i += 256) sE[i] = g_csr[beg + i];
    }
    int roff;
    {
        int nidx = nb + w * 16 + lane;      // lanes 0..16 used
        roff = g_row_off[min(nidx, N)];
    }
    __syncthreads();

    // ---- Stage 1: aggregation into sX (8 node pairs per warp) ----
    const int* ebase = fits ? sE : (g_csr + beg);
#pragma unroll 1
    for (int nn = 0; nn < 16; nn += 2) {
        int rb0 = __shfl_sync(0xffffffffu, roff, nn);
        int rb1 = __shfl_sync(0xffffffffu, roff, nn + 1);
        int re1 = __shfl_sync(0xffffffffu, roff, nn + 2);
        float ax0 = 0.f, ay0 = 0.f, ax1 = 0.f, ay1 = 0.f;
        agg_pair(xin, ebase + (rb0 - beg), rb1 - rb0,
                      ebase + (rb1 - beg), re1 - rb1, lane, ax0, ay0, ax1, ay1);
        int l0 = w * 16 + nn;
        float si0 = g_isq_in[min(nb + l0, N - 1)];
        float si1 = g_isq_in[min(nb + l0 + 1, N - 1)];
        sX[l0 * XP + 2 * lane]           = ax0 * si0;
        sX[l0 * XP + 2 * lane + 1]       = ay0 * si0;
        sX[(l0 + 1) * XP + 2 * lane]     = ax1 * si1;
        sX[(l0 + 1) * XP + 2 * lane + 1] = ay1 * si1;
    }
    __syncthreads();

    // ---- Stage 2: GEMM ----
    int q = w & 3;                 // column quarter (warp-uniform)
    int half = w >> 2;             // node half
    int n0 = half * 64 + 2 * lane; // local node (even); thread does n0, n0+1

    unsigned long long acc[2][8];
    {
        unsigned long long binit[8];
#pragma unroll
        for (int j = 0; j < 8; j++)
            binit[j] = pack2(bg[q * 16 + 2 * j], bg[q * 16 + 2 * j + 1]);
#pragma unroll
        for (int j = 0; j < 8; j++) { acc[0][j] = binit[j]; acc[1][j] = binit[j]; }
    }

    unsigned wbase = (unsigned)__cvta_generic_to_shared(&sW[q * 16]);
    unsigned xbase0 = (unsigned)__cvta_generic_to_shared(&sX[n0 * XP]);
    unsigned xbase1 = xbase0 + XP * 4;

#pragma unroll 8
    for (int k = 0; k < D; k++) {
        unsigned long long w2[8];
        unsigned waddr = wbase + k * (D * 4);
        asm("ld.shared.v2.u64 {%0,%1}, [%2];" : "=l"(w2[0]), "=l"(w2[1]) : "r"(waddr));
        asm("ld.shared.v2.u64 {%0,%1}, [%2];" : "=l"(w2[2]), "=l"(w2[3]) : "r"(waddr + 16));
        asm("ld.shared.v2.u64 {%0,%1}, [%2];" : "=l"(w2[4]), "=l"(w2[5]) : "r"(waddr + 32));
        asm("ld.shared.v2.u64 {%0,%1}, [%2];" : "=l"(w2[6]), "=l"(w2[7]) : "r"(waddr + 48));
        float a0, a1;
        asm("ld.shared.f32 %0, [%1];" : "=f"(a0) : "r"(xbase0 + k * 4));
        asm("ld.shared.f32 %0, [%1];" : "=f"(a1) : "r"(xbase1 + k * 4));
        unsigned long long a0p = pack2(a0, a0);
        unsigned long long a1p = pack2(a1, a1);
#pragma unroll
        for (int j = 0; j < 8; j++) {
            acc[0][j] = fma2(a0p, w2[j], acc[0][j]);
            acc[1][j] = fma2(a1p, w2[j], acc[1][j]);
        }
    }

#pragma unroll
    for (int m = 0; m < 2; m++) {
        int local = n0 + m;
        int node = nb + local;
        float v[16];
#pragma unroll
        for (int j = 0; j < 8; j++) unpack2(acc[m][j], v[2 * j], v[2 * j + 1]);
#pragma unroll
        for (int j = 0; j < 16; j++) v[j] = v[j] > 0.0f ? v[j] : 0.01f * v[j];

        if (!FUSE) {
            if (node < N) {
                float so = g_isq_out[node];       // fold next layer's source scale
                unsigned hp[8];
#pragma unroll
                for (int j = 0; j < 8; j++) {
                    __half2 h = __floats2half2_rn(v[2 * j] * so, v[2 * j + 1] * so);
                    hp[j] = *reinterpret_cast<unsigned*>(&h);
                }
                uint4* o = reinterpret_cast<uint4*>(out_h + (size_t)node * 32 + q * 8);
                o[0] = make_uint4(hp[0], hp[1], hp[2], hp[3]);
                o[1] = make_uint4(hp[4], hp[5], hp[6], hp[7]);
            }
        } else {
            float p0 = 0.0f, p1 = 0.0f;
#pragma unroll
            for (int j = 0; j < 16; j++) {
                int f = q * 16 + j;
                p0 = fmaf(v[j], sWc[2 * f + 0], p0);
                p1 = fmaf(v[j], sWc[2 * f + 1], p1);
            }
            sCls[local * 8 + q * 2 + 0] = p0;
            sCls[local * 8 + q * 2 + 1] = p1;
        }
    }

    if (FUSE) {
        __syncthreads();
        int local = tid >> 1;
        int o = tid & 1;
        int node = nb + local;
        if (node < N) {
            float p = sCls[local * 8 + 0 + o] + sCls[local * 8 + 2 + o]
                    + sCls[local * 8 + 4 + o] + sCls[local * 8 + 6 + o];
            out_f[(size_t)node * 2 + o] = p + bc[o];
        }
        // re-zero counters for next replay (replaces k_zero launch)
        int gs = gridDim.x * 256;
        for (int i = blockIdx.x * 256 + tid; i < N; i += gs) {
            g_cnt_out[i] = 0;
            g_cnt_in[i] = 0;
        }
    }
}

// ---------------------------------------------------------------------------
extern "C" void kernel_launch(void* const* d_in, const int* in_sizes, int n_in,
                              void* d_out, int out_size) {
    const float* x  = (const float*)d_in[0];
    const int*   src = (const int*)d_in[1];
    const int*   dst = (const int*)d_in[2];
    const float* W1 = (const float*)d_in[3];
    const float* b1 = (const float*)d_in[4];
    const float* W2 = (const float*)d_in[5];
    const float* b2 = (const float*)d_in[6];
    const float* Wc = (const float*)d_in[7];
    const float* bc = (const float*)d_in[8];
    float* out = (float*)d_out;

    int N = in_sizes[0] / D;
    int E = in_sizes[1];

    void *p_xh, *p_h1h;
    cudaGetSymbolAddress(&p_xh,  g_xh);
    cudaGetSymbolAddress(&p_h1h, g_h1h);

    size_t smem_bytes = (D * D + TILE * XP + TILE * 8 + 128 + ECAP) * sizeof(float);
    static bool attr_set = false;
    if (!attr_set) {
        cudaFuncSetAttribute(k_fused<false>, cudaFuncAttributeMaxDynamicSharedMemorySize,
                             (int)smem_bytes);
        cudaFuncSetAttribute(k_fused<true>, cudaFuncAttributeMaxDynamicSharedMemorySize,
                             (int)smem_bytes);
        attr_set = true;
    }

    int NB = (N + 255) / 256;
    int gblk = (N + TILE - 1) / TILE;

    // CSR build (padded to multiples of 8 with dummy node N)
    k_deg<<<(E + 255) / 256, 256>>>(src, dst, E);
    k_scan1<<<NB, 256>>>(N);
    k_scan23<<<NB, 256>>>(N, NB);
    k_place_prep<<<(E + 255) / 256, 256>>>(src, dst, x, E, N);

    // layer 1: xh -> h1h (fp16, isq_out pre-folded)
    k_fused<false><<<gblk, 256, smem_bytes>>>((const __half2*)p_xh, W1, b1,
                                              nullptr, nullptr,
                                              (__half2*)p_h1h, nullptr, N);
    // layer 2 + classifier (+ counter re-zero): h1h -> out
    k_fused<true><<<gblk, 256, smem_bytes>>>((const __half2*)p_h1h, W2, b2, Wc, bc,
                                             nullptr, out, N);
}